// round 2
// baseline (speedup 1.0000x reference)
#include <cuda_runtime.h>
#include <cuda_bf16.h>

// SelfAttention: B=32, D=2048
// q = x@Wq^T+bq ; k,v similarly
// scores[b,i,j] = q_i*k_j ; softmax over i ; out_i = sum_j w_ij * v_j
// Exact column max: m_j = k_j * (k_j>0 ? qmax : qmin)
// Pass1: S_j = sum_i exp(q_i k_j - m_j);  c_j = v_j / S_j
// Pass2: out_i = sum_j c_j * exp(q_i k_j - m_j)

#define BB 32
#define DD 2048
#define LOG2E 1.4426950408889634f

__device__ float g_q[BB * DD];
__device__ float g_k[BB * DD];
__device__ float g_v[BB * DD];
__device__ float g_c[BB * DD];

__device__ __forceinline__ float ex2f(float x) {
    float r;
    asm("ex2.approx.ftz.f32 %0, %1;" : "=f"(r) : "f"(x));
    return r;
}

// ---------------------------------------------------------------------------
// Kernel A: fused q/k/v GEMM.  out[m][n] = sum_k x[m][k]*W[n][k] + b[n]
// grid = 96 blocks (3 matrices x 32 n-tiles of 64), 256 threads.
// Tile: 32m x 64n, K-tiled by 32, double-buffered smem, thread tile 4m x 2n.
// ---------------------------------------------------------------------------
__global__ void __launch_bounds__(256) qkv_gemm(
    const float* __restrict__ x,
    const float* __restrict__ Wq, const float* __restrict__ bq,
    const float* __restrict__ Wk, const float* __restrict__ bk,
    const float* __restrict__ Wv, const float* __restrict__ bv)
{
    const int bx  = blockIdx.x;
    const int mat = bx >> 5;            // 0=q,1=k,2=v
    const int n0  = (bx & 31) * 64;

    const float* W    = (mat == 0) ? Wq : (mat == 1) ? Wk : Wv;
    const float* bias = (mat == 0) ? bq : (mat == 1) ? bk : bv;
    float*       dst  = (mat == 0) ? g_q : (mat == 1) ? g_k : g_v;

    __shared__ float xs[2][32][32];      // [buf][m][kk]  (reads broadcast)
    __shared__ float ws[2][32][66];      // [buf][kk][n]  (66: float2 aligned)

    const int tid = threadIdx.x;
    const int tn  = tid & 31;            // n-pair index 0..31
    const int tm  = tid >> 5;            // m-group 0..7

    float acc[4][2];
#pragma unroll
    for (int a = 0; a < 4; a++) { acc[a][0] = 0.f; acc[a][1] = 0.f; }

    float rx[4], rw[8];

    // prologue: load tile 0
#pragma unroll
    for (int t = 0; t < 4; t++) {
        int idx = tid + t * 256; int m = idx >> 5; int kk = idx & 31;
        rx[t] = x[m * DD + kk];
    }
#pragma unroll
    for (int t = 0; t < 8; t++) {
        int idx = tid + t * 256; int n = idx >> 5; int kk = idx & 31;
        rw[t] = W[(n0 + n) * DD + kk];
    }
#pragma unroll
    for (int t = 0; t < 4; t++) {
        int idx = tid + t * 256; int m = idx >> 5; int kk = idx & 31;
        xs[0][m][kk] = rx[t];
    }
#pragma unroll
    for (int t = 0; t < 8; t++) {
        int idx = tid + t * 256; int n = idx >> 5; int kk = idx & 31;
        ws[0][kk][n] = rw[t];
    }

    for (int kt = 0; kt < 64; kt++) {
        const int p = kt & 1;
        __syncthreads();

        if (kt < 63) {
            const int kbase = (kt + 1) * 32;
#pragma unroll
            for (int t = 0; t < 4; t++) {
                int idx = tid + t * 256; int m = idx >> 5; int kk = idx & 31;
                rx[t] = x[m * DD + kbase + kk];
            }
#pragma unroll
            for (int t = 0; t < 8; t++) {
                int idx = tid + t * 256; int n = idx >> 5; int kk = idx & 31;
                rw[t] = W[(n0 + n) * DD + kbase + kk];
            }
        }

#pragma unroll
        for (int kk = 0; kk < 32; kk++) {
            float x0 = xs[p][tm * 4 + 0][kk];
            float x1 = xs[p][tm * 4 + 1][kk];
            float x2 = xs[p][tm * 4 + 2][kk];
            float x3 = xs[p][tm * 4 + 3][kk];
            float2 w = *reinterpret_cast<const float2*>(&ws[p][kk][tn * 2]);
            acc[0][0] = fmaf(x0, w.x, acc[0][0]);
            acc[0][1] = fmaf(x0, w.y, acc[0][1]);
            acc[1][0] = fmaf(x1, w.x, acc[1][0]);
            acc[1][1] = fmaf(x1, w.y, acc[1][1]);
            acc[2][0] = fmaf(x2, w.x, acc[2][0]);
            acc[2][1] = fmaf(x2, w.y, acc[2][1]);
            acc[3][0] = fmaf(x3, w.x, acc[3][0]);
            acc[3][1] = fmaf(x3, w.y, acc[3][1]);
        }

        if (kt < 63) {
            const int np = p ^ 1;
#pragma unroll
            for (int t = 0; t < 4; t++) {
                int idx = tid + t * 256; int m = idx >> 5; int kk = idx & 31;
                xs[np][m][kk] = rx[t];
            }
#pragma unroll
            for (int t = 0; t < 8; t++) {
                int idx = tid + t * 256; int n = idx >> 5; int kk = idx & 31;
                ws[np][kk][n] = rw[t];
            }
        }
    }

    // epilogue
    const int ncol0 = n0 + tn * 2;
    const float b0 = bias[ncol0 + 0];
    const float b1 = bias[ncol0 + 1];
#pragma unroll
    for (int a = 0; a < 4; a++) {
        const int m = tm * 4 + a;
        dst[m * DD + ncol0 + 0] = acc[a][0] + b0;
        dst[m * DD + ncol0 + 1] = acc[a][1] + b1;
    }
}

// ---------------------------------------------------------------------------
// Block-level max/min reduction helper (512 threads). Returns via smem refs.
// ---------------------------------------------------------------------------
__device__ __forceinline__ void reduce_qmaxmin(
    float lmax, float lmin,
    float* redmax, float* redmin,
    float* s_qmax, float* s_qmin, int tid)
{
#pragma unroll
    for (int o = 16; o; o >>= 1) {
        lmax = fmaxf(lmax, __shfl_xor_sync(0xffffffffu, lmax, o));
        lmin = fminf(lmin, __shfl_xor_sync(0xffffffffu, lmin, o));
    }
    if ((tid & 31) == 0) { redmax[tid >> 5] = lmax; redmin[tid >> 5] = lmin; }
    __syncthreads();
    if (tid < 16) {
        lmax = redmax[tid];
        lmin = redmin[tid];
#pragma unroll
        for (int o = 8; o; o >>= 1) {
            lmax = fmaxf(lmax, __shfl_xor_sync(0xffffu, lmax, o));
            lmin = fminf(lmin, __shfl_xor_sync(0xffffu, lmin, o));
        }
        if (tid == 0) { *s_qmax = lmax; *s_qmin = lmin; }
    }
    __syncthreads();
}

// ---------------------------------------------------------------------------
// Kernel B: pass 1.  grid (4, 32), 512 threads. Thread handles one column j.
// ---------------------------------------------------------------------------
__global__ void __launch_bounds__(512) attn_pass1()
{
    const int b   = blockIdx.y;
    const int tid = threadIdx.x;

    __shared__ float qs[DD];
    __shared__ float redmax[16], redmin[16];
    __shared__ float s_qmax, s_qmin;

    const float* qrow = g_q + b * DD;
    float lmax = -3.402823466e38f, lmin = 3.402823466e38f;
#pragma unroll
    for (int t = tid; t < DD; t += 512) {
        float v = qrow[t];
        qs[t] = v;
        lmax = fmaxf(lmax, v);
        lmin = fminf(lmin, v);
    }
    reduce_qmaxmin(lmax, lmin, redmax, redmin, &s_qmax, &s_qmin, tid);

    const int   j  = blockIdx.x * 512 + tid;
    const float kj = g_k[b * DD + j];
    const float k2 = kj * LOG2E;
    const float nm2 = -(k2 * (kj > 0.f ? s_qmax : s_qmin));

    const float4* qs4 = reinterpret_cast<const float4*>(qs);
    float a0 = 0.f, a1 = 0.f, a2 = 0.f, a3 = 0.f;
#pragma unroll 4
    for (int i4 = 0; i4 < DD / 4; i4++) {
        float4 qv = qs4[i4];
        a0 += ex2f(fmaf(qv.x, k2, nm2));
        a1 += ex2f(fmaf(qv.y, k2, nm2));
        a2 += ex2f(fmaf(qv.z, k2, nm2));
        a3 += ex2f(fmaf(qv.w, k2, nm2));
    }
    const float S = (a0 + a1) + (a2 + a3);
    g_c[b * DD + j] = g_v[b * DD + j] / S;
}

// ---------------------------------------------------------------------------
// Kernel C: pass 2.  grid (4, 32), 512 threads. Thread handles one row i.
// ---------------------------------------------------------------------------
__global__ void __launch_bounds__(512) attn_pass2(float* __restrict__ out)
{
    const int b   = blockIdx.y;
    const int tid = threadIdx.x;

    __shared__ float  qs[DD];
    __shared__ float4 s4[DD];   // (k2_j, -m2_j, c_j, 0)
    __shared__ float  redmax[16], redmin[16];
    __shared__ float  s_qmax, s_qmin;

    const float* qrow = g_q + b * DD;
    float lmax = -3.402823466e38f, lmin = 3.402823466e38f;
#pragma unroll
    for (int t = tid; t < DD; t += 512) {
        float v = qrow[t];
        qs[t] = v;
        lmax = fmaxf(lmax, v);
        lmin = fminf(lmin, v);
    }
    reduce_qmaxmin(lmax, lmin, redmax, redmin, &s_qmax, &s_qmin, tid);

    const float qmx = s_qmax, qmn = s_qmin;
#pragma unroll
    for (int t = tid; t < DD; t += 512) {
        float kj = g_k[b * DD + t];
        float k2 = kj * LOG2E;
        float nm2 = -(k2 * (kj > 0.f ? qmx : qmn));
        float c  = g_c[b * DD + t];
        s4[t] = make_float4(k2, nm2, c, 0.f);
    }
    __syncthreads();

    const int   i  = blockIdx.x * 512 + tid;
    const float qi = qs[i];

    float a0 = 0.f, a1 = 0.f, a2 = 0.f, a3 = 0.f;
#pragma unroll 4
    for (int j = 0; j < DD; j += 4) {
        float4 p0 = s4[j + 0];
        float4 p1 = s4[j + 1];
        float4 p2 = s4[j + 2];
        float4 p3 = s4[j + 3];
        a0 = fmaf(p0.z, ex2f(fmaf(qi, p0.x, p0.y)), a0);
        a1 = fmaf(p1.z, ex2f(fmaf(qi, p1.x, p1.y)), a1);
        a2 = fmaf(p2.z, ex2f(fmaf(qi, p2.x, p2.y)), a2);
        a3 = fmaf(p3.z, ex2f(fmaf(qi, p3.x, p3.y)), a3);
    }
    out[b * DD + i] = (a0 + a1) + (a2 + a3);
}

// ---------------------------------------------------------------------------

extern "C" void kernel_launch(void* const* d_in, const int* in_sizes, int n_in,
                              void* d_out, int out_size)
{
    const float* x  = (const float*)d_in[0];
    const float* Wq = (const float*)d_in[1];
    const float* bq = (const float*)d_in[2];
    const float* Wk = (const float*)d_in[3];
    const float* bk = (const float*)d_in[4];
    const float* Wv = (const float*)d_in[5];
    const float* bv = (const float*)d_in[6];
    float* out = (float*)d_out;

    qkv_gemm<<<96, 256>>>(x, Wq, bq, Wk, bk, Wv, bv);
    attn_pass1<<<dim3(4, 32), 512>>>();
    attn_pass2<<<dim3(4, 32), 512>>>(out);
}

// round 3
// speedup vs baseline: 1.2838x; 1.2838x over previous
#include <cuda_runtime.h>
#include <cuda_bf16.h>

// SelfAttention: B=32, D=2048
// q = x@Wq^T+bq ; k,v similarly
// scores[b,i,j] = q_i*k_j ; softmax over i ; out_i = sum_j w_ij * v_j
// Exact column max: m_j = k_j * (k_j>0 ? qmax : qmin)
// Pass1: S_j = sum_i exp(q_i k_j - m_j);  c_j = v_j / S_j
// Pass2: out_i = sum_j c_j * exp(q_i k_j - m_j)

#define BB 32
#define DD 2048
#define LOG2E 1.4426950408889634f
#define KSPLIT 4
#define KCHUNK 512            // DD / KSPLIT

__device__ float g_q[BB * DD];
__device__ float g_k[BB * DD];
__device__ float g_v[BB * DD];
__device__ float g_c[BB * DD];
__device__ float g_part[KSPLIT][3 * BB * DD];   // GEMM partial sums per k-split

__device__ __forceinline__ float ex2f(float x) {
    float r;
    asm("ex2.approx.ftz.f32 %0, %1;" : "=f"(r) : "f"(x));
    return r;
}

// ---------------------------------------------------------------------------
// Kernel A: q/k/v GEMM partials.
// grid = 384 (= KSPLIT * 3 mats * 32 n-tiles), 128 threads.
// CTA tile: 32m x 64n over a 512-wide K chunk. Thread tile 4m x 4n.
// smem: xs k-major [kk][m] (pad 36), ws transposed [kk][n] (pad 68).
// Inner loop per kk per thread: 1 broadcast LDS.128 (x) + 1 LDS.128 (w) + 16 FFMA.
// ---------------------------------------------------------------------------
__global__ void __launch_bounds__(128) qkv_gemm_part(
    const float* __restrict__ x,
    const float* __restrict__ Wq,
    const float* __restrict__ Wk,
    const float* __restrict__ Wv)
{
    const int bx  = blockIdx.x;
    const int ks  = bx / 96;            // k-split index 0..3
    const int r   = bx % 96;
    const int mat = r >> 5;             // 0=q,1=k,2=v
    const int nt  = r & 31;
    const int n0  = nt * 64;
    const int k0  = ks * KCHUNK;

    const float* W = (mat == 0) ? Wq : (mat == 1) ? Wk : Wv;

    __shared__ float xs[2][32][36];     // [buf][kk][m], row pad 36 (16B aligned)
    __shared__ float ws[2][32][68];     // [buf][kk][n], row pad 68 (16B aligned)

    const int tid = threadIdx.x;
    const int tn  = tid & 15;           // n-quad 0..15  -> n = tn*4..tn*4+3
    const int tm  = tid >> 4;           // m-quad 0..7   -> m = tm*4..tm*4+3

    // loader indices
    const int xm  = tid >> 2;           // 0..31
    const int xk4 = (tid & 3) * 4;      // 0,4,8,12  (+16*l)
    const int wn  = tid >> 3;           // 0..15     (+16*l)
    const int wk4 = (tid & 7) * 4;      // 0..28

    float acc[4][4];
#pragma unroll
    for (int a = 0; a < 4; a++)
#pragma unroll
        for (int c = 0; c < 4; c++) acc[a][c] = 0.f;

    float4 xr[2], wr[4];

    // ---- prologue: load stage 0 ----
#pragma unroll
    for (int l = 0; l < 2; l++)
        xr[l] = *reinterpret_cast<const float4*>(&x[xm * DD + k0 + xk4 + 16 * l]);
#pragma unroll
    for (int l = 0; l < 4; l++)
        wr[l] = *reinterpret_cast<const float4*>(&W[(n0 + wn + 16 * l) * DD + k0 + wk4]);
#pragma unroll
    for (int l = 0; l < 2; l++) {
        const int kk = xk4 + 16 * l;
        xs[0][kk + 0][xm] = xr[l].x;
        xs[0][kk + 1][xm] = xr[l].y;
        xs[0][kk + 2][xm] = xr[l].z;
        xs[0][kk + 3][xm] = xr[l].w;
    }
#pragma unroll
    for (int l = 0; l < 4; l++) {
        const int n = wn + 16 * l;
        ws[0][wk4 + 0][n] = wr[l].x;
        ws[0][wk4 + 1][n] = wr[l].y;
        ws[0][wk4 + 2][n] = wr[l].z;
        ws[0][wk4 + 3][n] = wr[l].w;
    }

    const int NSTAGE = KCHUNK / 32;     // 16
    for (int kt = 0; kt < NSTAGE; kt++) {
        const int p = kt & 1;
        __syncthreads();

        if (kt < NSTAGE - 1) {
            const int kb = k0 + (kt + 1) * 32;
#pragma unroll
            for (int l = 0; l < 2; l++)
                xr[l] = *reinterpret_cast<const float4*>(&x[xm * DD + kb + xk4 + 16 * l]);
#pragma unroll
            for (int l = 0; l < 4; l++)
                wr[l] = *reinterpret_cast<const float4*>(&W[(n0 + wn + 16 * l) * DD + kb + wk4]);
        }

#pragma unroll
        for (int kk = 0; kk < 32; kk++) {
            const float4 xv = *reinterpret_cast<const float4*>(&xs[p][kk][tm * 4]);
            const float4 wv = *reinterpret_cast<const float4*>(&ws[p][kk][tn * 4]);
            acc[0][0] = fmaf(xv.x, wv.x, acc[0][0]);
            acc[0][1] = fmaf(xv.x, wv.y, acc[0][1]);
            acc[0][2] = fmaf(xv.x, wv.z, acc[0][2]);
            acc[0][3] = fmaf(xv.x, wv.w, acc[0][3]);
            acc[1][0] = fmaf(xv.y, wv.x, acc[1][0]);
            acc[1][1] = fmaf(xv.y, wv.y, acc[1][1]);
            acc[1][2] = fmaf(xv.y, wv.z, acc[1][2]);
            acc[1][3] = fmaf(xv.y, wv.w, acc[1][3]);
            acc[2][0] = fmaf(xv.z, wv.x, acc[2][0]);
            acc[2][1] = fmaf(xv.z, wv.y, acc[2][1]);
            acc[2][2] = fmaf(xv.z, wv.z, acc[2][2]);
            acc[2][3] = fmaf(xv.z, wv.w, acc[2][3]);
            acc[3][0] = fmaf(xv.w, wv.x, acc[3][0]);
            acc[3][1] = fmaf(xv.w, wv.y, acc[3][1]);
            acc[3][2] = fmaf(xv.w, wv.z, acc[3][2]);
            acc[3][3] = fmaf(xv.w, wv.w, acc[3][3]);
        }

        if (kt < NSTAGE - 1) {
            const int np = p ^ 1;
#pragma unroll
            for (int l = 0; l < 2; l++) {
                const int kk = xk4 + 16 * l;
                xs[np][kk + 0][xm] = xr[l].x;
                xs[np][kk + 1][xm] = xr[l].y;
                xs[np][kk + 2][xm] = xr[l].z;
                xs[np][kk + 3][xm] = xr[l].w;
            }
#pragma unroll
            for (int l = 0; l < 4; l++) {
                const int n = wn + 16 * l;
                ws[np][wk4 + 0][n] = wr[l].x;
                ws[np][wk4 + 1][n] = wr[l].y;
                ws[np][wk4 + 2][n] = wr[l].z;
                ws[np][wk4 + 3][n] = wr[l].w;
            }
        }
    }

    // epilogue: store partials (float4)
    float* dst = g_part[ks];
#pragma unroll
    for (int a = 0; a < 4; a++) {
        const int m = tm * 4 + a;
        float4 v = make_float4(acc[a][0], acc[a][1], acc[a][2], acc[a][3]);
        *reinterpret_cast<float4*>(&dst[(mat * BB + m) * DD + n0 + tn * 4]) = v;
    }
}

// ---------------------------------------------------------------------------
// Kernel A2: combine k-split partials + bias -> g_q/g_k/g_v.
// grid = 96, 512 threads: 49152 float4 elements total.
// ---------------------------------------------------------------------------
__global__ void __launch_bounds__(512) qkv_combine(
    const float* __restrict__ bq,
    const float* __restrict__ bk,
    const float* __restrict__ bv)
{
    const int idx4 = blockIdx.x * 512 + threadIdx.x;   // 0..49151
    const float4 p0 = reinterpret_cast<const float4*>(g_part[0])[idx4];
    const float4 p1 = reinterpret_cast<const float4*>(g_part[1])[idx4];
    const float4 p2 = reinterpret_cast<const float4*>(g_part[2])[idx4];
    const float4 p3 = reinterpret_cast<const float4*>(g_part[3])[idx4];

    const int mat  = idx4 / (BB * DD / 4);       // 0..2
    const int rem  = idx4 % (BB * DD / 4);
    const int col4 = idx4 % (DD / 4);

    const float* bias = (mat == 0) ? bq : (mat == 1) ? bk : bv;
    const float4 b4 = reinterpret_cast<const float4*>(bias)[col4];

    float4 o;
    o.x = (p0.x + p1.x) + (p2.x + p3.x) + b4.x;
    o.y = (p0.y + p1.y) + (p2.y + p3.y) + b4.y;
    o.z = (p0.z + p1.z) + (p2.z + p3.z) + b4.z;
    o.w = (p0.w + p1.w) + (p2.w + p3.w) + b4.w;

    float* dst = (mat == 0) ? g_q : (mat == 1) ? g_k : g_v;
    reinterpret_cast<float4*>(dst)[rem] = o;
}

// ---------------------------------------------------------------------------
// Block-level max/min reduction helper (512 threads).
// ---------------------------------------------------------------------------
__device__ __forceinline__ void reduce_qmaxmin(
    float lmax, float lmin,
    float* redmax, float* redmin,
    float* s_qmax, float* s_qmin, int tid)
{
#pragma unroll
    for (int o = 16; o; o >>= 1) {
        lmax = fmaxf(lmax, __shfl_xor_sync(0xffffffffu, lmax, o));
        lmin = fminf(lmin, __shfl_xor_sync(0xffffffffu, lmin, o));
    }
    if ((tid & 31) == 0) { redmax[tid >> 5] = lmax; redmin[tid >> 5] = lmin; }
    __syncthreads();
    if (tid < 16) {
        lmax = redmax[tid];
        lmin = redmin[tid];
#pragma unroll
        for (int o = 8; o; o >>= 1) {
            lmax = fmaxf(lmax, __shfl_xor_sync(0xffffu, lmax, o));
            lmin = fminf(lmin, __shfl_xor_sync(0xffffu, lmin, o));
        }
        if (tid == 0) { *s_qmax = lmax; *s_qmin = lmin; }
    }
    __syncthreads();
}

// ---------------------------------------------------------------------------
// Kernel B: pass 1.  grid (4, 32), 512 threads. Thread handles one column j.
// ---------------------------------------------------------------------------
__global__ void __launch_bounds__(512) attn_pass1()
{
    const int b   = blockIdx.y;
    const int tid = threadIdx.x;

    __shared__ float qs[DD];
    __shared__ float redmax[16], redmin[16];
    __shared__ float s_qmax, s_qmin;

    const float* qrow = g_q + b * DD;
    float lmax = -3.402823466e38f, lmin = 3.402823466e38f;
#pragma unroll
    for (int t = tid; t < DD; t += 512) {
        float v = qrow[t];
        qs[t] = v;
        lmax = fmaxf(lmax, v);
        lmin = fminf(lmin, v);
    }
    reduce_qmaxmin(lmax, lmin, redmax, redmin, &s_qmax, &s_qmin, tid);

    const int   j  = blockIdx.x * 512 + tid;
    const float kj = g_k[b * DD + j];
    const float k2 = kj * LOG2E;
    const float nm2 = -(k2 * (kj > 0.f ? s_qmax : s_qmin));

    const float4* qs4 = reinterpret_cast<const float4*>(qs);
    float a0 = 0.f, a1 = 0.f, a2 = 0.f, a3 = 0.f;
#pragma unroll 4
    for (int i4 = 0; i4 < DD / 4; i4++) {
        float4 qv = qs4[i4];
        a0 += ex2f(fmaf(qv.x, k2, nm2));
        a1 += ex2f(fmaf(qv.y, k2, nm2));
        a2 += ex2f(fmaf(qv.z, k2, nm2));
        a3 += ex2f(fmaf(qv.w, k2, nm2));
    }
    const float S = (a0 + a1) + (a2 + a3);
    g_c[b * DD + j] = g_v[b * DD + j] / S;
}

// ---------------------------------------------------------------------------
// Kernel C: pass 2.  grid (4, 32), 512 threads. Thread handles one row i.
// ---------------------------------------------------------------------------
__global__ void __launch_bounds__(512) attn_pass2(float* __restrict__ out)
{
    const int b   = blockIdx.y;
    const int tid = threadIdx.x;

    __shared__ float  qs[DD];
    __shared__ float4 s4[DD];   // (k2_j, -m2_j, c_j, 0)
    __shared__ float  redmax[16], redmin[16];
    __shared__ float  s_qmax, s_qmin;

    const float* qrow = g_q + b * DD;
    float lmax = -3.402823466e38f, lmin = 3.402823466e38f;
#pragma unroll
    for (int t = tid; t < DD; t += 512) {
        float v = qrow[t];
        qs[t] = v;
        lmax = fmaxf(lmax, v);
        lmin = fminf(lmin, v);
    }
    reduce_qmaxmin(lmax, lmin, redmax, redmin, &s_qmax, &s_qmin, tid);

    const float qmx = s_qmax, qmn = s_qmin;
#pragma unroll
    for (int t = tid; t < DD; t += 512) {
        float kj = g_k[b * DD + t];
        float k2 = kj * LOG2E;
        float nm2 = -(k2 * (kj > 0.f ? qmx : qmn));
        float c  = g_c[b * DD + t];
        s4[t] = make_float4(k2, nm2, c, 0.f);
    }
    __syncthreads();

    const int   i  = blockIdx.x * 512 + tid;
    const float qi = qs[i];

    float a0 = 0.f, a1 = 0.f, a2 = 0.f, a3 = 0.f;
#pragma unroll 4
    for (int j = 0; j < DD; j += 4) {
        float4 p0 = s4[j + 0];
        float4 p1 = s4[j + 1];
        float4 p2 = s4[j + 2];
        float4 p3 = s4[j + 3];
        a0 = fmaf(p0.z, ex2f(fmaf(qi, p0.x, p0.y)), a0);
        a1 = fmaf(p1.z, ex2f(fmaf(qi, p1.x, p1.y)), a1);
        a2 = fmaf(p2.z, ex2f(fmaf(qi, p2.x, p2.y)), a2);
        a3 = fmaf(p3.z, ex2f(fmaf(qi, p3.x, p3.y)), a3);
    }
    out[b * DD + i] = (a0 + a1) + (a2 + a3);
}

// ---------------------------------------------------------------------------

extern "C" void kernel_launch(void* const* d_in, const int* in_sizes, int n_in,
                              void* d_out, int out_size)
{
    const float* x  = (const float*)d_in[0];
    const float* Wq = (const float*)d_in[1];
    const float* bq = (const float*)d_in[2];
    const float* Wk = (const float*)d_in[3];
    const float* bk = (const float*)d_in[4];
    const float* Wv = (const float*)d_in[5];
    const float* bv = (const float*)d_in[6];
    float* out = (float*)d_out;

    qkv_gemm_part<<<384, 128>>>(x, Wq, Wk, Wv);
    qkv_combine<<<96, 512>>>(bq, bk, bv);
    attn_pass1<<<dim3(4, 32), 512>>>();
    attn_pass2<<<dim3(4, 32), 512>>>(out);
}